// round 1
// baseline (speedup 1.0000x reference)
#include <cuda_runtime.h>

// Problem dims (fixed by the dataset)
#define O_DIM  4096   // compressed weight rows (active output rows)
#define I_DIM  2048   // compressed weight cols
#define K_ACT  2048   // active k (len(idx))
#define N_TOK  4096   // tokens (n)
#define M_DENSE 8192  // dense output rows
// out = [M_DENSE, N_TOK] fp32

// 32 MB scratch: gathered dense-active weight Wg[o][j] = W[indices[o]-row, idx[j]-col]
__device__ float g_Wg[(size_t)O_DIM * K_ACT];

// ---------------------------------------------------------------------------
// f32x2 packed-FMA helpers (FFMA2: double-rate fp32 on sm_103a, PTX-only)
// ---------------------------------------------------------------------------
__device__ __forceinline__ unsigned long long pack2(float lo, float hi) {
    unsigned long long r;
    asm("mov.b64 %0, {%1, %2};" : "=l"(r) : "f"(lo), "f"(hi));
    return r;
}
__device__ __forceinline__ void unpack2(unsigned long long v, float& lo, float& hi) {
    asm("mov.b64 {%0, %1}, %2;" : "=f"(lo), "=f"(hi) : "l"(v));
}
__device__ __forceinline__ unsigned long long ffma2(unsigned long long a,
                                                    unsigned long long b,
                                                    unsigned long long c) {
    unsigned long long d;
    asm("fma.rn.f32x2 %0, %1, %2, %3;" : "=l"(d) : "l"(a), "l"(b), "l"(c));
    return d;
}

// ---------------------------------------------------------------------------
// Kernel 1: build Wg[o][j] by direct gather (no scatter needed).
//   kd = idx[j]; g = kd/4; p = kd%4
//   Wg = weight[o,2g]   if metadata[o,2g]   == p
//      = weight[o,2g+1] if metadata[o,2g+1] == p
//      = 0 otherwise
// ---------------------------------------------------------------------------
__global__ void build_wg_kernel(const float* __restrict__ weight,
                                const int*   __restrict__ idx,
                                const int*   __restrict__ metadata) {
    int t = blockIdx.x * blockDim.x + threadIdx.x;   // 0 .. O_DIM*K_ACT-1
    int j = t & (K_ACT - 1);
    int o = t >> 11;                                  // K_ACT = 2^11
    int kd = __ldg(idx + j);
    int g  = kd >> 2;
    int p  = kd & 3;
    const int2 md = *reinterpret_cast<const int2*>(metadata + (size_t)o * I_DIM + 2 * g);
    float v = 0.0f;
    if (md.x == p)      v = __ldg(weight + (size_t)o * I_DIM + 2 * g);
    else if (md.y == p) v = __ldg(weight + (size_t)o * I_DIM + 2 * g + 1);
    g_Wg[(size_t)t] = v;
}

// ---------------------------------------------------------------------------
// Kernel 2: zero-fill output (inactive rows must be 0; output is poisoned)
// ---------------------------------------------------------------------------
__global__ void zero_out_kernel(float4* __restrict__ out) {
    size_t t = (size_t)blockIdx.x * blockDim.x + threadIdx.x;
    out[t] = make_float4(0.f, 0.f, 0.f, 0.f);
}

// ---------------------------------------------------------------------------
// Kernel 3: C[o,n] = sum_j Wg[o,j] * input[n,j], written to out[indices[o], n]
// 128x128 tile, BK=16, 256 threads, 8x8 microtile via packed FFMA2.
// Both operands are K-major (row-major with K contiguous) -> symmetric loads.
// ---------------------------------------------------------------------------
__global__ __launch_bounds__(256, 2)
void sgemm_scatter_kernel(const float* __restrict__ B,        // input [N_TOK, K_ACT]
                          const int*   __restrict__ indices,  // [O_DIM]
                          float*       __restrict__ out) {    // [M_DENSE, N_TOK]
    __shared__ float As[16][128];
    __shared__ float Bs[16][128];

    const int bm  = blockIdx.y * 128;   // over o
    const int bn  = blockIdx.x * 128;   // over n
    const int tid = threadIdx.x;
    const int tx  = tid & 15;           // n-subtile
    const int ty  = tid >> 4;           // m-subtile

    const float* A = g_Wg;

    unsigned long long acc[8][4];       // 8 rows x 4 float2-pairs (8 cols)
#pragma unroll
    for (int i = 0; i < 8; i++)
#pragma unroll
        for (int jj = 0; jj < 4; jj++) acc[i][jj] = 0ULL;

    for (int k0 = 0; k0 < K_ACT; k0 += 16) {
        // cooperative load: 128 rows x 16 k per operand = 512 float4 / operand
#pragma unroll
        for (int l = 0; l < 2; l++) {
            int li  = l * 256 + tid;
            int row = li >> 2;
            int kc  = (li & 3) << 2;
            float4 va = *reinterpret_cast<const float4*>(
                A + (size_t)(bm + row) * K_ACT + k0 + kc);
            As[kc + 0][row] = va.x; As[kc + 1][row] = va.y;
            As[kc + 2][row] = va.z; As[kc + 3][row] = va.w;
            float4 vb = *reinterpret_cast<const float4*>(
                B + (size_t)(bn + row) * K_ACT + k0 + kc);
            Bs[kc + 0][row] = vb.x; Bs[kc + 1][row] = vb.y;
            Bs[kc + 2][row] = vb.z; Bs[kc + 3][row] = vb.w;
        }
        __syncthreads();

#pragma unroll
        for (int k = 0; k < 16; k++) {
            float a[8];
            unsigned long long b[4];
#pragma unroll
            for (int i = 0; i < 8; i++) a[i] = As[k][ty * 8 + i];
#pragma unroll
            for (int jj = 0; jj < 4; jj++)
                b[jj] = *reinterpret_cast<const unsigned long long*>(
                    &Bs[k][tx * 8 + jj * 2]);
#pragma unroll
            for (int i = 0; i < 8; i++) {
                unsigned long long ad = pack2(a[i], a[i]);
#pragma unroll
                for (int jj = 0; jj < 4; jj++)
                    acc[i][jj] = ffma2(ad, b[jj], acc[i][jj]);
            }
        }
        __syncthreads();
    }

    // epilogue: scatter each m-row to its dense output row
#pragma unroll
    for (int i = 0; i < 8; i++) {
        int o   = bm + ty * 8 + i;
        int row = __ldg(indices + o);
        float* dst = out + (size_t)row * N_TOK + bn + tx * 8;
        float4 v0, v1;
        unpack2(acc[i][0], v0.x, v0.y);
        unpack2(acc[i][1], v0.z, v0.w);
        unpack2(acc[i][2], v1.x, v1.y);
        unpack2(acc[i][3], v1.z, v1.w);
        *reinterpret_cast<float4*>(dst)     = v0;
        *reinterpret_cast<float4*>(dst + 4) = v1;
    }
}

// ---------------------------------------------------------------------------
extern "C" void kernel_launch(void* const* d_in, const int* in_sizes, int n_in,
                              void* d_out, int out_size) {
    const float* input    = (const float*)d_in[0];
    const int*   idx      = (const int*)  d_in[1];
    const float* weight   = (const float*)d_in[2];
    const int*   indices  = (const int*)  d_in[3];
    const int*   metadata = (const int*)  d_in[4];

    // defensive: idx has K_ACT elements, indices has O_DIM — disambiguate by size
    if (in_sizes[1] == O_DIM && in_sizes[3] == K_ACT) {
        const int* t = idx; idx = indices; indices = t;
    }

    float* out = (float*)d_out;

    // 1) gather compressed weight -> dense-active Wg [O_DIM, K_ACT]
    build_wg_kernel<<<(O_DIM * K_ACT) / 256, 256>>>(weight, idx, metadata);

    // 2) zero the full dense output (inactive rows stay 0)
    zero_out_kernel<<<(M_DENSE * N_TOK / 4) / 256, 256>>>((float4*)out);

    // 3) dense GEMM over active rows/cols, scatter rows via indices
    dim3 grid(N_TOK / 128, O_DIM / 128);
    sgemm_scatter_kernel<<<grid, 256>>>(input, indices, out);
}

// round 3
// speedup vs baseline: 2.9571x; 2.9571x over previous
#include <cuda_runtime.h>
#include <cstdint>

// Problem dims (fixed by the dataset)
#define O_DIM   4096
#define I_DIM   2048
#define K_ACT   2048
#define N_TOK   4096
#define M_DENSE 8192

// Scratch (device globals; allocation-free rule)
__device__ float g_Wg[(size_t)O_DIM * K_ACT];   // gathered weight, tf32-rounded
__device__ float g_Bc[(size_t)N_TOK * K_ACT];   // activations, tf32-rounded

__device__ __forceinline__ uint32_t tf32_rna(float f) {
    uint32_t u;
    asm("cvt.rna.tf32.f32 %0, %1;" : "=r"(u) : "f"(f));
    return u;
}
__device__ __forceinline__ uint32_t f2u(float f) { return __float_as_uint(f); }

// ===========================================================================
// Kernel 1: gather compressed weight -> Wg[o][j], tf32-rounded
// ===========================================================================
__global__ void build_wg_kernel(const float* __restrict__ weight,
                                const int*   __restrict__ idx,
                                const int*   __restrict__ metadata) {
    int t = blockIdx.x * blockDim.x + threadIdx.x;
    int j = t & (K_ACT - 1);
    int o = t >> 11;
    int kd = __ldg(idx + j);
    int g  = kd >> 2;
    int p  = kd & 3;
    const int2 md = *reinterpret_cast<const int2*>(metadata + (size_t)o * I_DIM + 2 * g);
    float v = 0.0f;
    if (md.x == p)      v = __ldg(weight + (size_t)o * I_DIM + 2 * g);
    else if (md.y == p) v = __ldg(weight + (size_t)o * I_DIM + 2 * g + 1);
    reinterpret_cast<uint32_t*>(g_Wg)[t] = tf32_rna(v);
}

// ===========================================================================
// Kernel 2: tf32-round activations
// ===========================================================================
__global__ void convert_b_kernel(const float4* __restrict__ input) {
    int t = blockIdx.x * blockDim.x + threadIdx.x;   // over float4s
    float4 v = input[t];
    uint4 r;
    r.x = tf32_rna(v.x); r.y = tf32_rna(v.y);
    r.z = tf32_rna(v.z); r.w = tf32_rna(v.w);
    reinterpret_cast<uint4*>(g_Bc)[t] = r;
}

// ===========================================================================
// Kernel 3: zero-fill output
// ===========================================================================
__global__ void zero_out_kernel(float4* __restrict__ out) {
    size_t t = (size_t)blockIdx.x * blockDim.x + threadIdx.x;
    out[t] = make_float4(0.f, 0.f, 0.f, 0.f);
}

// ===========================================================================
// Kernel 4: tf32 mma.sync GEMM with row-scatter epilogue
//   C[o, n] = sum_j Wg[o, j] * Bc[n, j]  -> out[indices[o], n]
//   CTA: 128(M) x 256(N), K-chunk 32, 512 threads = 16 warps (4x4),
//   warp tile 32(M) x 64(N) = 2 x 8 m16n8k8 tiles. 2-stage cp.async.
// ===========================================================================
#define KC      32
#define KITERS  (K_ACT / KC)          // 64
#define LDSTR   36                    // padded floats per smem row (144B, 16B-mult)
#define A_FLTS  (128 * LDSTR)         // 4608
#define B_FLTS  (256 * LDSTR)         // 9216
#define STG_FLTS (A_FLTS + B_FLTS)    // 13824 floats = 55296 B
#define SMEM_DYN (2 * STG_FLTS * 4)   // 110592 B

__device__ __forceinline__ void mma_tf32(float* c,
    uint32_t a0, uint32_t a1, uint32_t a2, uint32_t a3,
    uint32_t b0, uint32_t b1) {
    asm volatile(
        "mma.sync.aligned.m16n8k8.row.col.f32.tf32.tf32.f32 "
        "{%0,%1,%2,%3}, {%4,%5,%6,%7}, {%8,%9}, {%0,%1,%2,%3};"
        : "+f"(c[0]), "+f"(c[1]), "+f"(c[2]), "+f"(c[3])
        : "r"(a0), "r"(a1), "r"(a2), "r"(a3), "r"(b0), "r"(b1));
}
__device__ __forceinline__ void cp_async16(void* dst_smem, const void* src) {
    uint32_t d;
    asm("{ .reg .u64 t; cvta.to.shared.u64 t, %1; cvt.u32.u64 %0, t; }"
        : "=r"(d) : "l"(dst_smem));
    asm volatile("cp.async.cg.shared.global [%0], [%1], 16;" :: "r"(d), "l"(src));
}

__global__ __launch_bounds__(512, 1)
void gemm_mma_kernel(const int* __restrict__ indices,
                     float*     __restrict__ out) {
    extern __shared__ float smem[];
    const float* Ag = g_Wg;
    const float* Bg = g_Bc;

    const int tid  = threadIdx.x;
    const int lane = tid & 31;
    const int wid  = tid >> 5;
    const int wm   = wid >> 2;        // 0..3  -> m offset wm*32
    const int wn   = wid & 3;         // 0..3  -> n offset wn*64
    const int bm   = blockIdx.y * 128;
    const int bn   = blockIdx.x * 256;

    float acc[2][8][4];
#pragma unroll
    for (int mi = 0; mi < 2; mi++)
#pragma unroll
        for (int ni = 0; ni < 8; ni++)
#pragma unroll
            for (int q = 0; q < 4; q++) acc[mi][ni][q] = 0.0f;

    // ---- cp.async stage loader: A 128x32, B 256x32 (16B per op) ----
    auto load_stage = [&](int kc, int s) {
        float* As = smem + s * STG_FLTS;
        float* Bs = As + A_FLTS;
#pragma unroll
        for (int i = 0; i < 2; i++) {               // A: 1024 float4
            int f = i * 512 + tid;
            int row = f >> 3, c4 = (f & 7) << 2;
            cp_async16(As + row * LDSTR + c4,
                       Ag + (size_t)(bm + row) * K_ACT + kc * KC + c4);
        }
#pragma unroll
        for (int i = 0; i < 4; i++) {               // B: 2048 float4
            int f = i * 512 + tid;
            int row = f >> 3, c4 = (f & 7) << 2;
            cp_async16(Bs + row * LDSTR + c4,
                       Bg + (size_t)(bn + row) * K_ACT + kc * KC + c4);
        }
    };

    load_stage(0, 0);
    asm volatile("cp.async.commit_group;" ::: "memory");

    for (int kc = 0; kc < KITERS; kc++) {
        if (kc + 1 < KITERS) load_stage(kc + 1, (kc + 1) & 1);
        asm volatile("cp.async.commit_group;" ::: "memory");
        asm volatile("cp.async.wait_group 1;" ::: "memory");
        __syncthreads();

        const float* As = smem + (kc & 1) * STG_FLTS;
        const float* Bs = As + A_FLTS;
#pragma unroll
        for (int ks = 0; ks < 4; ks++) {
            const int c0 = ks * 8 + (lane & 3);
            uint32_t a[2][4];
#pragma unroll
            for (int mi = 0; mi < 2; mi++) {
                int r = wm * 32 + mi * 16 + (lane >> 2);
                a[mi][0] = f2u(As[r * LDSTR + c0]);
                a[mi][1] = f2u(As[(r + 8) * LDSTR + c0]);
                a[mi][2] = f2u(As[r * LDSTR + c0 + 4]);
                a[mi][3] = f2u(As[(r + 8) * LDSTR + c0 + 4]);
            }
            uint32_t b[8][2];
#pragma unroll
            for (int ni = 0; ni < 8; ni++) {
                int n = wn * 64 + ni * 8 + (lane >> 2);
                b[ni][0] = f2u(Bs[n * LDSTR + c0]);
                b[ni][1] = f2u(Bs[n * LDSTR + c0 + 4]);
            }
#pragma unroll
            for (int mi = 0; mi < 2; mi++)
#pragma unroll
                for (int ni = 0; ni < 8; ni++)
                    mma_tf32(acc[mi][ni], a[mi][0], a[mi][1], a[mi][2], a[mi][3],
                             b[ni][0], b[ni][1]);
        }
        __syncthreads();
    }

    // ---- epilogue: scatter rows via indices ----
#pragma unroll
    for (int mi = 0; mi < 2; mi++) {
        int r0 = bm + wm * 32 + mi * 16 + (lane >> 2);
        int o0 = __ldg(indices + r0);
        int o1 = __ldg(indices + r0 + 8);
        float* d0 = out + (size_t)o0 * N_TOK + bn + wn * 64 + 2 * (lane & 3);
        float* d1 = out + (size_t)o1 * N_TOK + bn + wn * 64 + 2 * (lane & 3);
#pragma unroll
        for (int ni = 0; ni < 8; ni++) {
            float2 v0 = make_float2(acc[mi][ni][0], acc[mi][ni][1]);
            float2 v1 = make_float2(acc[mi][ni][2], acc[mi][ni][3]);
            *reinterpret_cast<float2*>(d0 + ni * 8) = v0;
            *reinterpret_cast<float2*>(d1 + ni * 8) = v1;
        }
    }
}

// ===========================================================================
// Host launcher
// ===========================================================================
extern "C" void kernel_launch(void* const* d_in, const int* in_sizes, int n_in,
                              void* d_out, int out_size) {
    const float* input    = (const float*)d_in[0];
    const int*   idx      = (const int*)  d_in[1];
    const float* weight   = (const float*)d_in[2];
    const int*   indices  = (const int*)  d_in[3];
    const int*   metadata = (const int*)  d_in[4];
    if (in_sizes[1] == O_DIM && in_sizes[3] == K_ACT) {
        const int* t = idx; idx = indices; indices = t;
    }
    float* out = (float*)d_out;

    cudaFuncSetAttribute(gemm_mma_kernel,
                         cudaFuncAttributeMaxDynamicSharedMemorySize, SMEM_DYN);

    // 1) gather + tf32-round weight
    build_wg_kernel<<<(O_DIM * K_ACT) / 256, 256>>>(weight, idx, metadata);
    // 2) tf32-round activations
    convert_b_kernel<<<(N_TOK * K_ACT / 4) / 256, 256>>>((const float4*)input);
    // 3) zero dense output
    zero_out_kernel<<<(M_DENSE * N_TOK / 4) / 256, 256>>>((float4*)out);
    // 4) tensor-core GEMM + scatter
    dim3 grid(N_TOK / 256, O_DIM / 128);   // 16 x 32
    gemm_mma_kernel<<<grid, 512, SMEM_DYN>>>(indices, out);
}

// round 4
// speedup vs baseline: 3.3685x; 1.1391x over previous
#include <cuda_runtime.h>
#include <cstdint>

// Problem dims (fixed by the dataset)
#define O_DIM   4096
#define I_DIM   2048
#define K_ACT   2048
#define N_TOK   4096
#define M_DENSE 8192

// Scratch (device globals; allocation-free rule)
__device__ float g_Wg[(size_t)O_DIM * K_ACT];   // gathered weight, tf32-rounded
__device__ float g_Bc[(size_t)N_TOK * K_ACT];   // activations, tf32-rounded

__device__ __forceinline__ uint32_t tf32_rna(float f) {
    uint32_t u;
    asm("cvt.rna.tf32.f32 %0, %1;" : "=r"(u) : "f"(f));
    return u;
}
__device__ __forceinline__ uint32_t f2u(float f) { return __float_as_uint(f); }

// ===========================================================================
// Kernel 1: gather compressed weight -> Wg[o][j], tf32-rounded
// ===========================================================================
__global__ void build_wg_kernel(const float* __restrict__ weight,
                                const int*   __restrict__ idx,
                                const int*   __restrict__ metadata) {
    int t = blockIdx.x * blockDim.x + threadIdx.x;
    int j = t & (K_ACT - 1);
    int o = t >> 11;
    int kd = __ldg(idx + j);
    int g  = kd >> 2;
    int p  = kd & 3;
    const int2 md = *reinterpret_cast<const int2*>(metadata + (size_t)o * I_DIM + 2 * g);
    float v = 0.0f;
    if (md.x == p)      v = __ldg(weight + (size_t)o * I_DIM + 2 * g);
    else if (md.y == p) v = __ldg(weight + (size_t)o * I_DIM + 2 * g + 1);
    reinterpret_cast<uint32_t*>(g_Wg)[t] = tf32_rna(v);
}

// ===========================================================================
// Kernel 2: tf32-round activations
// ===========================================================================
__global__ void convert_b_kernel(const float4* __restrict__ input) {
    int t = blockIdx.x * blockDim.x + threadIdx.x;   // over float4s
    float4 v = input[t];
    uint4 r;
    r.x = tf32_rna(v.x); r.y = tf32_rna(v.y);
    r.z = tf32_rna(v.z); r.w = tf32_rna(v.w);
    reinterpret_cast<uint4*>(g_Bc)[t] = r;
}

// ===========================================================================
// Kernel 3: zero-fill output
// ===========================================================================
__global__ void zero_out_kernel(float4* __restrict__ out) {
    size_t t = (size_t)blockIdx.x * blockDim.x + threadIdx.x;
    out[t] = make_float4(0.f, 0.f, 0.f, 0.f);
}

// ===========================================================================
// Kernel 4: tf32 mma.sync GEMM with row-scatter epilogue
//   C[o, n] = sum_j Wg[o, j] * Bc[n, j]  -> out[indices[o], n]
//   CTA: 128(M) x 128(N), K-chunk 32, 256 threads = 8 warps (4m x 2n),
//   warp tile 32(M) x 64(N) = 2 x 8 m16n8k8 tiles. 2-stage cp.async.
//   2 CTAs/SM -> independent barrier domains keep the HMMA pipe fed.
// ===========================================================================
#define MT      128
#define NT      128
#define KC      32
#define KITERS  (K_ACT / KC)          // 64
#define LDSTR   36                    // padded floats per smem row (144B)
#define A_FLTS  (MT * LDSTR)          // 4608
#define B_FLTS  (NT * LDSTR)          // 4608
#define STG_FLTS (A_FLTS + B_FLTS)    // 9216 floats = 36864 B
#define SMEM_DYN (2 * STG_FLTS * 4)   // 73728 B

__device__ __forceinline__ void mma_tf32(float* c,
    uint32_t a0, uint32_t a1, uint32_t a2, uint32_t a3,
    uint32_t b0, uint32_t b1) {
    asm volatile(
        "mma.sync.aligned.m16n8k8.row.col.f32.tf32.tf32.f32 "
        "{%0,%1,%2,%3}, {%4,%5,%6,%7}, {%8,%9}, {%0,%1,%2,%3};"
        : "+f"(c[0]), "+f"(c[1]), "+f"(c[2]), "+f"(c[3])
        : "r"(a0), "r"(a1), "r"(a2), "r"(a3), "r"(b0), "r"(b1));
}
__device__ __forceinline__ void cp_async16(void* dst_smem, const void* src) {
    uint32_t d;
    asm("{ .reg .u64 t; cvta.to.shared.u64 t, %1; cvt.u32.u64 %0, t; }"
        : "=r"(d) : "l"(dst_smem));
    asm volatile("cp.async.cg.shared.global [%0], [%1], 16;" :: "r"(d), "l"(src));
}

__global__ __launch_bounds__(256, 2)
void gemm_mma_kernel(const int* __restrict__ indices,
                     float*     __restrict__ out) {
    extern __shared__ float smem[];
    const float* Ag = g_Wg;
    const float* Bg = g_Bc;

    const int tid  = threadIdx.x;
    const int lane = tid & 31;
    const int wid  = tid >> 5;
    const int wm   = wid >> 1;        // 0..3  -> m offset wm*32
    const int wn   = wid & 1;         // 0..1  -> n offset wn*64
    const int bm   = blockIdx.y * MT;
    const int bn   = blockIdx.x * NT;

    float acc[2][8][4];
#pragma unroll
    for (int mi = 0; mi < 2; mi++)
#pragma unroll
        for (int ni = 0; ni < 8; ni++)
#pragma unroll
            for (int q = 0; q < 4; q++) acc[mi][ni][q] = 0.0f;

    // ---- cp.async stage loader: A 128x32, B 128x32 (16B per op) ----
    auto load_stage = [&](int kc, int s) {
        float* As = smem + s * STG_FLTS;
        float* Bs = As + A_FLTS;
#pragma unroll
        for (int i = 0; i < 4; i++) {               // A: 1024 float4
            int f = i * 256 + tid;
            int row = f >> 3, c4 = (f & 7) << 2;
            cp_async16(As + row * LDSTR + c4,
                       Ag + (size_t)(bm + row) * K_ACT + kc * KC + c4);
        }
#pragma unroll
        for (int i = 0; i < 4; i++) {               // B: 1024 float4
            int f = i * 256 + tid;
            int row = f >> 3, c4 = (f & 7) << 2;
            cp_async16(Bs + row * LDSTR + c4,
                       Bg + (size_t)(bn + row) * K_ACT + kc * KC + c4);
        }
    };

    load_stage(0, 0);
    asm volatile("cp.async.commit_group;" ::: "memory");

    for (int kc = 0; kc < KITERS; kc++) {
        if (kc + 1 < KITERS) load_stage(kc + 1, (kc + 1) & 1);
        asm volatile("cp.async.commit_group;" ::: "memory");
        asm volatile("cp.async.wait_group 1;" ::: "memory");
        __syncthreads();

        const float* As = smem + (kc & 1) * STG_FLTS;
        const float* Bs = As + A_FLTS;
#pragma unroll
        for (int ks = 0; ks < 4; ks++) {
            const int c0 = ks * 8 + (lane & 3);
            uint32_t a[2][4];
#pragma unroll
            for (int mi = 0; mi < 2; mi++) {
                int r = wm * 32 + mi * 16 + (lane >> 2);
                a[mi][0] = f2u(As[r * LDSTR + c0]);
                a[mi][1] = f2u(As[(r + 8) * LDSTR + c0]);
                a[mi][2] = f2u(As[r * LDSTR + c0 + 4]);
                a[mi][3] = f2u(As[(r + 8) * LDSTR + c0 + 4]);
            }
            uint32_t b[8][2];
#pragma unroll
            for (int ni = 0; ni < 8; ni++) {
                int n = wn * 64 + ni * 8 + (lane >> 2);
                b[ni][0] = f2u(Bs[n * LDSTR + c0]);
                b[ni][1] = f2u(Bs[n * LDSTR + c0 + 4]);
            }
#pragma unroll
            for (int mi = 0; mi < 2; mi++)
#pragma unroll
                for (int ni = 0; ni < 8; ni++)
                    mma_tf32(acc[mi][ni], a[mi][0], a[mi][1], a[mi][2], a[mi][3],
                             b[ni][0], b[ni][1]);
        }
        __syncthreads();
    }

    // ---- epilogue: scatter rows via indices ----
#pragma unroll
    for (int mi = 0; mi < 2; mi++) {
        int r0 = bm + wm * 32 + mi * 16 + (lane >> 2);
        int o0 = __ldg(indices + r0);
        int o1 = __ldg(indices + r0 + 8);
        float* d0 = out + (size_t)o0 * N_TOK + bn + wn * 64 + 2 * (lane & 3);
        float* d1 = out + (size_t)o1 * N_TOK + bn + wn * 64 + 2 * (lane & 3);
#pragma unroll
        for (int ni = 0; ni < 8; ni++) {
            float2 v0 = make_float2(acc[mi][ni][0], acc[mi][ni][1]);
            float2 v1 = make_float2(acc[mi][ni][2], acc[mi][ni][3]);
            *reinterpret_cast<float2*>(d0 + ni * 8) = v0;
            *reinterpret_cast<float2*>(d1 + ni * 8) = v1;
        }
    }
}

// ===========================================================================
// Host launcher
// ===========================================================================
extern "C" void kernel_launch(void* const* d_in, const int* in_sizes, int n_in,
                              void* d_out, int out_size) {
    const float* input    = (const float*)d_in[0];
    const int*   idx      = (const int*)  d_in[1];
    const float* weight   = (const float*)d_in[2];
    const int*   indices  = (const int*)  d_in[3];
    const int*   metadata = (const int*)  d_in[4];
    if (in_sizes[1] == O_DIM && in_sizes[3] == K_ACT) {
        const int* t = idx; idx = indices; indices = t;
    }
    float* out = (float*)d_out;

    cudaFuncSetAttribute(gemm_mma_kernel,
                         cudaFuncAttributeMaxDynamicSharedMemorySize, SMEM_DYN);

    // 1) gather + tf32-round weight
    build_wg_kernel<<<(O_DIM * K_ACT) / 256, 256>>>(weight, idx, metadata);
    // 2) tf32-round activations
    convert_b_kernel<<<(N_TOK * K_ACT / 4) / 256, 256>>>((const float4*)input);
    // 3) zero dense output
    zero_out_kernel<<<(M_DENSE * N_TOK / 4) / 256, 256>>>((float4*)out);
    // 4) tensor-core GEMM + scatter
    dim3 grid(N_TOK / NT, O_DIM / MT);   // 32 x 32
    gemm_mma_kernel<<<grid, 256, SMEM_DYN>>>(indices, out);
}